// round 13
// baseline (speedup 1.0000x reference)
#include <cuda_runtime.h>
#include <cuda_fp16.h>
#include <cstdint>
#include <cstddef>

#define N_NODES 12288
#define IN_F    256
#define OUT_F   64
#define JSPLIT  3
#define JRANGE  (N_NODES / JSPLIT)   // 4096
#define BI      128                  // i-rows per CTA
#define NTILES  (JRANGE / 64)        // 64

// h as fp16, transposed (feature-major): g_qt[f][j]
__device__ __half g_qt[OUT_F * N_NODES];               // 1.6 MB
__device__ float  g_part[JSPLIT][N_NODES * OUT_F];     // 9.4 MB
__device__ int    g_deg[JSPLIT][N_NODES];

// ---------------- helpers ----------------
__device__ __forceinline__ uint32_t smem_u32(const void* p) {
    uint32_t a;
    asm("{ .reg .u64 t; cvta.to.shared.u64 t, %1; cvt.u32.u64 %0, t; }"
        : "=r"(a) : "l"(p));
    return a;
}
__device__ __forceinline__ void sts64(uint32_t addr, uint32_t a, uint32_t b) {
    asm volatile("st.shared.v2.b32 [%0], {%1,%2};" :: "r"(addr), "r"(a), "r"(b) : "memory");
}
__device__ __forceinline__ void cp_async16(uint32_t dst, const void* src) {
    asm volatile("cp.async.cg.shared.global [%0], [%1], 16;" :: "r"(dst), "l"(src) : "memory");
}
__device__ __forceinline__ void ldsm4(uint32_t* r, uint32_t addr) {
    asm volatile("ldmatrix.sync.aligned.m8n8.x4.shared.b16 {%0,%1,%2,%3}, [%4];"
        : "=r"(r[0]), "=r"(r[1]), "=r"(r[2]), "=r"(r[3]) : "r"(addr));
}
__device__ __forceinline__ void mma16816(float* c, const uint32_t* a,
                                         uint32_t b0, uint32_t b1) {
    asm volatile(
        "mma.sync.aligned.m16n8k16.row.col.f32.f16.f16.f32 "
        "{%0,%1,%2,%3},{%4,%5,%6,%7},{%8,%9},{%0,%1,%2,%3};"
        : "+f"(c[0]), "+f"(c[1]), "+f"(c[2]), "+f"(c[3])
        : "r"(a[0]), "r"(a[1]), "r"(a[2]), "r"(a[3]), "r"(b0), "r"(b1));
}
__device__ __forceinline__ uint32_t sw128(uint32_t off) {
    return off ^ ((off >> 3) & 0x70u);
}

// ======================= Kernel 1: h = x @ W -> fp16 transposed =======================
// Occupancy-first: 768 CTAs x 256 thr; CTA = 16 rows x 64 feats; thread = 1 row x 4 feats.
// x staged once (16x257), W in 8 chunks of 32 rows. ~41 resident warps/SM.
__global__ void __launch_bounds__(256)
k_gemm_h(const float* __restrict__ x, const float* __restrict__ W) {
    __shared__ float x_s[16][257];
    __shared__ float w_s[32][68];
    const int tid = threadIdx.x;
    const int ti  = tid & 15;            // row within CTA
    const int tf  = tid >> 4;            // 0..15 -> 4 feats each
    const int rBase = blockIdx.x * 16;

    // stage x: 16x256 floats = 1024 float4, 4 per thread (scalar STS, pad 257)
    #pragma unroll
    for (int m = 0; m < 4; m++) {
        int idx = tid + m * 256;
        int row = idx >> 6;
        int c4  = (idx & 63) << 2;
        float4 v = *reinterpret_cast<const float4*>(
            x + (size_t)(rBase + row) * IN_F + c4);
        float* dst = &x_s[row][c4];
        dst[0] = v.x; dst[1] = v.y; dst[2] = v.z; dst[3] = v.w;
    }

    float acc[4] = {0.f, 0.f, 0.f, 0.f};

    for (int kc = 0; kc < 8; kc++) {
        __syncthreads();
        // stage W rows [kc*32, +32) x 64 feats: 512 float4, 2 per thread
        #pragma unroll
        for (int m = 0; m < 2; m++) {
            int idx = tid + m * 256;
            int row = idx >> 4;
            int c4  = (idx & 15) << 2;
            *reinterpret_cast<float4*>(&w_s[row][c4]) =
                *reinterpret_cast<const float4*>(
                    W + (size_t)(kc * 32 + row) * OUT_F + c4);
        }
        __syncthreads();
        #pragma unroll 16
        for (int kk = 0; kk < 32; kk++) {
            float xv = x_s[ti][kc * 32 + kk];
            float4 wv = *reinterpret_cast<const float4*>(&w_s[kk][tf * 4]);
            acc[0] += xv * wv.x; acc[1] += xv * wv.y;
            acc[2] += xv * wv.z; acc[3] += xv * wv.w;
        }
    }

    const int j = rBase + ti;
    #pragma unroll
    for (int u = 0; u < 4; u++)
        g_qt[(size_t)(tf * 4 + u) * N_NODES + j] = __float2half_rn(acc[u]);
}

// ======================= Kernel 2: fp16 HMMA masked aggregation (unchanged) ==========
// partial[js][i,f] = sum_{j in split} mask[i,j] * h_fp16[j,f]
// CTA tile 128(i) x 64(f) x 64(j). Warps 4M x 2N (M=32, N=32 each).
// smem: A fp16 [2][128][64] @0 (32KB), B fp16 [3][64][64] @32768 (24KB)
#define SMEM_AGG (32768 + 24576 + 1024)
__global__ void __launch_bounds__(256, 2)
k_aggregate(const int* __restrict__ adj) {
    extern __shared__ __align__(1024) unsigned char smem[];
    const int tid   = threadIdx.x;
    const int lane  = tid & 31;
    const int w     = tid >> 5;
    const int wm    = w & 3;        // M quarter (32 rows)
    const int wn    = w >> 2;       // N half (32 feats)
    const int iBase = blockIdx.x * BI;
    const int js    = blockIdx.y;
    const int jBeg  = js * JRANGE;

    const uint32_t sbase = (smem_u32(smem) + 1023u) & ~1023u;
    const uint32_t offA  = sbase;
    const uint32_t offB  = sbase + 32768;

    // ---- staging geometry ----
    const uint32_t A_SW0 = sw128((uint32_t)((tid >> 4) * 128 + (tid & 15) * 8));
    const int4* aT = reinterpret_cast<const int4*>(
        adj + (size_t)(iBase + (tid >> 4)) * N_NODES + jBeg) + (tid & 15);
    const uint32_t B_SW0 = sw128((uint32_t)((tid >> 3) * 128 + (tid & 7) * 16));
    const __half* bT = g_qt + (size_t)(tid >> 3) * N_NODES + jBeg + (tid & 7) * 8;

    // ---- ldmatrix lane geometry ----
    const uint32_t a_ch = (uint32_t)((lane >> 4) << 4);
    const uint32_t AR0  = (uint32_t)((wm * 32 + (lane & 15)) * 128 + ((lane & 7) << 4));
    const int b_n       = (lane & 7) + ((lane >> 4) << 3);
    const uint32_t b_cb = (lane & 8) ? 16u : 0u;
    const uint32_t BR0  = (uint32_t)((wn * 32 + b_n) * 128 + ((b_n & 7) << 4));

    // ---- prologue ----
    cp_async16(offB + B_SW0, bT);
    cp_async16(offB + 4096 + B_SW0, bT + (size_t)32 * N_NODES);
    asm volatile("cp.async.commit_group;" ::: "memory");
    const __half* bC = bT + 64;
    int4 rA[8];
    #pragma unroll
    for (int k = 0; k < 8; k++) rA[k] = __ldg(aT + (size_t)k * 16 * (N_NODES / 4));
    aT += 16;

    float acc[2][4][4];
    #pragma unroll
    for (int mi = 0; mi < 2; mi++)
        #pragma unroll
        for (int nj = 0; nj < 4; nj++)
            #pragma unroll
            for (int q = 0; q < 4; q++) acc[mi][nj][q] = 0.f;
    int dacc[8] = {0,0,0,0,0,0,0,0};

    for (int t = 0; t < NTILES; t++) {
        const uint32_t aBuf = offA + (uint32_t)(t & 1) * 16384;
        const uint32_t bBuf = offB + (uint32_t)(t % 3) * 8192;

        // 1. convert + STS A(t) as fp16 0/1; degree via dp4a
        #pragma unroll
        for (int k = 0; k < 8; k++) {
            uint32_t t0 = __byte_perm((uint32_t)rA[k].x, (uint32_t)rA[k].y, 0x7430);
            uint32_t t1 = __byte_perm((uint32_t)rA[k].z, (uint32_t)rA[k].w, 0x7430);
            dacc[k] = __dp4a((int)t0, 0x01010101, dacc[k]);
            dacc[k] = __dp4a((int)t1, 0x01010101, dacc[k]);
            sts64(aBuf + A_SW0 + (uint32_t)k * 2048, t0 * 0x3C00u, t1 * 0x3C00u);
        }
        // 2. prefetch tile t+1
        if (t + 1 < NTILES) {
            uint32_t bDst = offB + (uint32_t)((t + 1) % 3) * 8192;
            cp_async16(bDst + B_SW0, bC);
            cp_async16(bDst + 4096 + B_SW0, bC + (size_t)32 * N_NODES);
            asm volatile("cp.async.commit_group;" ::: "memory");
            bC += 64;
            #pragma unroll
            for (int k = 0; k < 8; k++) rA[k] = __ldg(aT + (size_t)k * 16 * (N_NODES / 4));
            aT += 16;
            asm volatile("cp.async.wait_group 1;" ::: "memory");
        } else {
            asm volatile("cp.async.wait_group 0;" ::: "memory");
        }
        __syncthreads();

        // 3. HMMA on tile t
        #pragma unroll
        for (int kk = 0; kk < 4; kk++) {
            const uint32_t cb = (uint32_t)(kk * 32);
            uint32_t B0[4], B1[4];
            ldsm4(B0, (bBuf + BR0)        ^ (cb + b_cb));
            ldsm4(B1, (bBuf + BR0 + 2048) ^ (cb + b_cb));
            #pragma unroll
            for (int mi = 0; mi < 2; mi++) {
                uint32_t A0[4];
                ldsm4(A0, (aBuf + AR0 + (uint32_t)mi * 2048) ^ (cb + a_ch));
                mma16816(acc[mi][0], A0, B0[0], B0[1]);
                mma16816(acc[mi][1], A0, B0[2], B0[3]);
                mma16816(acc[mi][2], A0, B1[0], B1[1]);
                mma16816(acc[mi][3], A0, B1[2], B1[3]);
            }
        }
        __syncthreads();
    }

    // ---- epilogue: write partials ----
    {
        const int g8 = lane >> 2;
        const int cp = (lane & 3) * 2;
        #pragma unroll
        for (int mi = 0; mi < 2; mi++) {
            int r = iBase + wm * 32 + mi * 16 + g8;
            #pragma unroll
            for (int nj = 0; nj < 4; nj++) {
                int col = wn * 32 + nj * 8 + cp;
                float2 v0 = make_float2(acc[mi][nj][0], acc[mi][nj][1]);
                float2 v1 = make_float2(acc[mi][nj][2], acc[mi][nj][3]);
                *reinterpret_cast<float2*>(&g_part[js][(size_t)r * OUT_F + col]) = v0;
                *reinterpret_cast<float2*>(&g_part[js][(size_t)(r + 8) * OUT_F + col]) = v1;
            }
        }
    }

    // degree
    #pragma unroll
    for (int k = 0; k < 8; k++) {
        int v = dacc[k];
        v += __shfl_down_sync(0xffffffffu, v, 8, 16);
        v += __shfl_down_sync(0xffffffffu, v, 4, 16);
        v += __shfl_down_sync(0xffffffffu, v, 2, 16);
        v += __shfl_down_sync(0xffffffffu, v, 1, 16);
        if ((tid & 15) == 0)
            g_deg[js][iBase + k * 16 + (tid >> 4)] = v;
    }
}

// ================ Kernel 3: out = elu(sum(partials)/deg) ================
__global__ void __launch_bounds__(256)
k_finalize(float* __restrict__ out) {
    int g = blockIdx.x * 256 + threadIdx.x;
    int i = g >> 6;
    float s = g_part[0][g] + g_part[1][g] + g_part[2][g];
    float d = (float)(g_deg[0][i] + g_deg[1][i] + g_deg[2][i]);
    float v = s / d;
    out[g] = (v > 0.f) ? v : expm1f(v);
}

// =========================== launch ===========================
extern "C" void kernel_launch(void* const* d_in, const int* in_sizes, int n_in,
                              void* d_out, int out_size) {
    const int* adj = nullptr;
    const float* x = nullptr;
    const float* W = nullptr;
    for (int k = 0; k < n_in; k++) {
        long long sz = in_sizes[k];
        if (sz == (long long)N_NODES * N_NODES)      adj = (const int*)d_in[k];
        else if (sz == (long long)N_NODES * IN_F)    x = (const float*)d_in[k];
        else if (sz == (long long)IN_F * OUT_F)      W = (const float*)d_in[k];
    }
    float* out = (float*)d_out;

    cudaFuncSetAttribute(k_aggregate, cudaFuncAttributeMaxDynamicSharedMemorySize, SMEM_AGG);

    k_gemm_h<<<N_NODES / 16, 256>>>(x, W);
    k_aggregate<<<dim3(N_NODES / BI, JSPLIT), 256, SMEM_AGG>>>(adj);
    k_finalize<<<(N_NODES * OUT_F) / 256, 256>>>(out);
}

// round 14
// speedup vs baseline: 1.0498x; 1.0498x over previous
#include <cuda_runtime.h>
#include <cuda_fp16.h>
#include <cstdint>
#include <cstddef>

#define N_NODES 12288
#define IN_F    256
#define OUT_F   64
#define JSPLIT  3
#define JRANGE  (N_NODES / JSPLIT)   // 4096
#define BI      128                  // i-rows per CTA
#define NTILES  (JRANGE / 64)        // 64

// h as fp16, transposed (feature-major): g_qt[f][j]
__device__ __half g_qt[OUT_F * N_NODES];               // 1.6 MB
__device__ float  g_part[JSPLIT][N_NODES * OUT_F];     // 9.4 MB
__device__ int    g_deg[JSPLIT][N_NODES];

// ---------------- helpers ----------------
__device__ __forceinline__ uint32_t smem_u32(const void* p) {
    uint32_t a;
    asm("{ .reg .u64 t; cvta.to.shared.u64 t, %1; cvt.u32.u64 %0, t; }"
        : "=r"(a) : "l"(p));
    return a;
}
__device__ __forceinline__ void sts64(uint32_t addr, uint32_t a, uint32_t b) {
    asm volatile("st.shared.v2.b32 [%0], {%1,%2};" :: "r"(addr), "r"(a), "r"(b) : "memory");
}
__device__ __forceinline__ void cp_async16(uint32_t dst, const void* src) {
    asm volatile("cp.async.cg.shared.global [%0], [%1], 16;" :: "r"(dst), "l"(src) : "memory");
}
__device__ __forceinline__ void ldsm4(uint32_t* r, uint32_t addr) {
    asm volatile("ldmatrix.sync.aligned.m8n8.x4.shared.b16 {%0,%1,%2,%3}, [%4];"
        : "=r"(r[0]), "=r"(r[1]), "=r"(r[2]), "=r"(r[3]) : "r"(addr));
}
__device__ __forceinline__ void mma16816(float* c, const uint32_t* a,
                                         uint32_t b0, uint32_t b1) {
    asm volatile(
        "mma.sync.aligned.m16n8k16.row.col.f32.f16.f16.f32 "
        "{%0,%1,%2,%3},{%4,%5,%6,%7},{%8,%9},{%0,%1,%2,%3};"
        : "+f"(c[0]), "+f"(c[1]), "+f"(c[2]), "+f"(c[3])
        : "r"(a[0]), "r"(a[1]), "r"(a[2]), "r"(a[3]), "r"(b0), "r"(b1));
}
__device__ __forceinline__ uint32_t sw128(uint32_t off) {
    return off ^ ((off >> 3) & 0x70u);
}
// ---- packed f32x2 ----
__device__ __forceinline__ unsigned long long pack2(float x) {
    unsigned long long r;
    asm("mov.b64 %0, {%1, %1};" : "=l"(r) : "f"(x));
    return r;
}
__device__ __forceinline__ void ffma2(unsigned long long& acc,
                                      unsigned long long a,
                                      unsigned long long b) {
    asm("fma.rn.f32x2 %0, %1, %2, %0;" : "+l"(acc) : "l"(a), "l"(b));
}
__device__ __forceinline__ float2 unpack2(unsigned long long v) {
    float2 r;
    asm("mov.b64 {%0, %1}, %2;" : "=f"(r.x), "=f"(r.y) : "l"(v));
    return r;
}

// ======================= Kernel 1: h = x @ W -> fp16 transposed (FFMA2) ================
// 256 thr, CTA = 32 rows x 64 feats, thread = 1 row x 8 feats (4 f32x2 accs).
// Per k: 1 x LDS.32 (conflict-free) + 2 warp-uniform w LDS.128 + 4 FFMA2.
__global__ void __launch_bounds__(256)
k_gemm_h(const float* __restrict__ x, const float* __restrict__ W) {
    __shared__ float x_s[32][257];     // bank = ti + k (pad 257)
    __shared__ float w_s[32][68];      // row 272B (16B-aligned)
    const int tid = threadIdx.x;
    const int ti  = tid & 31;          // row
    const int tf  = tid >> 5;          // 0..7 -> 8 feats (warp-uniform)
    const int rBase = blockIdx.x * 32;

    // stage all x for CTA: 2048 float4, 8 per thread (scalar STS, pad 257)
    #pragma unroll 4
    for (int m = 0; m < 8; m++) {
        int idx = tid + m * 256;
        int row = idx >> 6;
        int c4  = (idx & 63) << 2;
        float4 v = *reinterpret_cast<const float4*>(
            x + (size_t)(rBase + row) * IN_F + c4);
        float* dst = &x_s[row][c4];
        dst[0] = v.x; dst[1] = v.y; dst[2] = v.z; dst[3] = v.w;
    }

    unsigned long long acc[4] = {0ULL, 0ULL, 0ULL, 0ULL};

    for (int kc = 0; kc < 8; kc++) {
        __syncthreads();
        // stage W rows [kc*32, +32) x 64 feats: 512 float4, 2 per thread
        #pragma unroll
        for (int m = 0; m < 2; m++) {
            int idx = tid + m * 256;
            int row = idx >> 4;
            int c4  = (idx & 15) << 2;
            *reinterpret_cast<float4*>(&w_s[row][c4]) =
                *reinterpret_cast<const float4*>(
                    W + (size_t)(kc * 32 + row) * OUT_F + c4);
        }
        __syncthreads();
        #pragma unroll 8
        for (int kk = 0; kk < 32; kk++) {
            unsigned long long xp = pack2(x_s[ti][kc * 32 + kk]);
            ulonglong2 w01 = *reinterpret_cast<const ulonglong2*>(&w_s[kk][tf * 8]);
            ulonglong2 w23 = *reinterpret_cast<const ulonglong2*>(&w_s[kk][tf * 8 + 4]);
            ffma2(acc[0], xp, w01.x);
            ffma2(acc[1], xp, w01.y);
            ffma2(acc[2], xp, w23.x);
            ffma2(acc[3], xp, w23.y);
        }
    }

    const int j = rBase + ti;
    #pragma unroll
    for (int u = 0; u < 4; u++) {
        float2 p = unpack2(acc[u]);
        g_qt[(size_t)(tf * 8 + 2 * u)     * N_NODES + j] = __float2half_rn(p.x);
        g_qt[(size_t)(tf * 8 + 2 * u + 1) * N_NODES + j] = __float2half_rn(p.y);
    }
}

// ======================= Kernel 2: fp16 HMMA masked aggregation (unchanged) ==========
// partial[js][i,f] = sum_{j in split} mask[i,j] * h_fp16[j,f]
// CTA tile 128(i) x 64(f) x 64(j). Warps 4M x 2N (M=32, N=32 each).
// smem: A fp16 [2][128][64] @0 (32KB), B fp16 [3][64][64] @32768 (24KB)
#define SMEM_AGG (32768 + 24576 + 1024)
__global__ void __launch_bounds__(256, 2)
k_aggregate(const int* __restrict__ adj) {
    extern __shared__ __align__(1024) unsigned char smem[];
    const int tid   = threadIdx.x;
    const int lane  = tid & 31;
    const int w     = tid >> 5;
    const int wm    = w & 3;        // M quarter (32 rows)
    const int wn    = w >> 2;       // N half (32 feats)
    const int iBase = blockIdx.x * BI;
    const int js    = blockIdx.y;
    const int jBeg  = js * JRANGE;

    const uint32_t sbase = (smem_u32(smem) + 1023u) & ~1023u;
    const uint32_t offA  = sbase;
    const uint32_t offB  = sbase + 32768;

    // ---- staging geometry ----
    const uint32_t A_SW0 = sw128((uint32_t)((tid >> 4) * 128 + (tid & 15) * 8));
    const int4* aT = reinterpret_cast<const int4*>(
        adj + (size_t)(iBase + (tid >> 4)) * N_NODES + jBeg) + (tid & 15);
    const uint32_t B_SW0 = sw128((uint32_t)((tid >> 3) * 128 + (tid & 7) * 16));
    const __half* bT = g_qt + (size_t)(tid >> 3) * N_NODES + jBeg + (tid & 7) * 8;

    // ---- ldmatrix lane geometry ----
    const uint32_t a_ch = (uint32_t)((lane >> 4) << 4);
    const uint32_t AR0  = (uint32_t)((wm * 32 + (lane & 15)) * 128 + ((lane & 7) << 4));
    const int b_n       = (lane & 7) + ((lane >> 4) << 3);
    const uint32_t b_cb = (lane & 8) ? 16u : 0u;
    const uint32_t BR0  = (uint32_t)((wn * 32 + b_n) * 128 + ((b_n & 7) << 4));

    // ---- prologue ----
    cp_async16(offB + B_SW0, bT);
    cp_async16(offB + 4096 + B_SW0, bT + (size_t)32 * N_NODES);
    asm volatile("cp.async.commit_group;" ::: "memory");
    const __half* bC = bT + 64;
    int4 rA[8];
    #pragma unroll
    for (int k = 0; k < 8; k++) rA[k] = __ldg(aT + (size_t)k * 16 * (N_NODES / 4));
    aT += 16;

    float acc[2][4][4];
    #pragma unroll
    for (int mi = 0; mi < 2; mi++)
        #pragma unroll
        for (int nj = 0; nj < 4; nj++)
            #pragma unroll
            for (int q = 0; q < 4; q++) acc[mi][nj][q] = 0.f;
    int dacc[8] = {0,0,0,0,0,0,0,0};

    for (int t = 0; t < NTILES; t++) {
        const uint32_t aBuf = offA + (uint32_t)(t & 1) * 16384;
        const uint32_t bBuf = offB + (uint32_t)(t % 3) * 8192;

        // 1. convert + STS A(t) as fp16 0/1; degree via dp4a
        #pragma unroll
        for (int k = 0; k < 8; k++) {
            uint32_t t0 = __byte_perm((uint32_t)rA[k].x, (uint32_t)rA[k].y, 0x7430);
            uint32_t t1 = __byte_perm((uint32_t)rA[k].z, (uint32_t)rA[k].w, 0x7430);
            dacc[k] = __dp4a((int)t0, 0x01010101, dacc[k]);
            dacc[k] = __dp4a((int)t1, 0x01010101, dacc[k]);
            sts64(aBuf + A_SW0 + (uint32_t)k * 2048, t0 * 0x3C00u, t1 * 0x3C00u);
        }
        // 2. prefetch tile t+1
        if (t + 1 < NTILES) {
            uint32_t bDst = offB + (uint32_t)((t + 1) % 3) * 8192;
            cp_async16(bDst + B_SW0, bC);
            cp_async16(bDst + 4096 + B_SW0, bC + (size_t)32 * N_NODES);
            asm volatile("cp.async.commit_group;" ::: "memory");
            bC += 64;
            #pragma unroll
            for (int k = 0; k < 8; k++) rA[k] = __ldg(aT + (size_t)k * 16 * (N_NODES / 4));
            aT += 16;
            asm volatile("cp.async.wait_group 1;" ::: "memory");
        } else {
            asm volatile("cp.async.wait_group 0;" ::: "memory");
        }
        __syncthreads();

        // 3. HMMA on tile t
        #pragma unroll
        for (int kk = 0; kk < 4; kk++) {
            const uint32_t cb = (uint32_t)(kk * 32);
            uint32_t B0[4], B1[4];
            ldsm4(B0, (bBuf + BR0)        ^ (cb + b_cb));
            ldsm4(B1, (bBuf + BR0 + 2048) ^ (cb + b_cb));
            #pragma unroll
            for (int mi = 0; mi < 2; mi++) {
                uint32_t A0[4];
                ldsm4(A0, (aBuf + AR0 + (uint32_t)mi * 2048) ^ (cb + a_ch));
                mma16816(acc[mi][0], A0, B0[0], B0[1]);
                mma16816(acc[mi][1], A0, B0[2], B0[3]);
                mma16816(acc[mi][2], A0, B1[0], B1[1]);
                mma16816(acc[mi][3], A0, B1[2], B1[3]);
            }
        }
        __syncthreads();
    }

    // ---- epilogue: write partials ----
    {
        const int g8 = lane >> 2;
        const int cp = (lane & 3) * 2;
        #pragma unroll
        for (int mi = 0; mi < 2; mi++) {
            int r = iBase + wm * 32 + mi * 16 + g8;
            #pragma unroll
            for (int nj = 0; nj < 4; nj++) {
                int col = wn * 32 + nj * 8 + cp;
                float2 v0 = make_float2(acc[mi][nj][0], acc[mi][nj][1]);
                float2 v1 = make_float2(acc[mi][nj][2], acc[mi][nj][3]);
                *reinterpret_cast<float2*>(&g_part[js][(size_t)r * OUT_F + col]) = v0;
                *reinterpret_cast<float2*>(&g_part[js][(size_t)(r + 8) * OUT_F + col]) = v1;
            }
        }
    }

    // degree
    #pragma unroll
    for (int k = 0; k < 8; k++) {
        int v = dacc[k];
        v += __shfl_down_sync(0xffffffffu, v, 8, 16);
        v += __shfl_down_sync(0xffffffffu, v, 4, 16);
        v += __shfl_down_sync(0xffffffffu, v, 2, 16);
        v += __shfl_down_sync(0xffffffffu, v, 1, 16);
        if ((tid & 15) == 0)
            g_deg[js][iBase + k * 16 + (tid >> 4)] = v;
    }
}

// ================ Kernel 3: out = elu(sum(partials)/deg) ================
__global__ void __launch_bounds__(256)
k_finalize(float* __restrict__ out) {
    int g = blockIdx.x * 256 + threadIdx.x;
    int i = g >> 6;
    float s = g_part[0][g] + g_part[1][g] + g_part[2][g];
    float d = (float)(g_deg[0][i] + g_deg[1][i] + g_deg[2][i]);
    float v = s / d;
    out[g] = (v > 0.f) ? v : expm1f(v);
}

// =========================== launch ===========================
extern "C" void kernel_launch(void* const* d_in, const int* in_sizes, int n_in,
                              void* d_out, int out_size) {
    const int* adj = nullptr;
    const float* x = nullptr;
    const float* W = nullptr;
    for (int k = 0; k < n_in; k++) {
        long long sz = in_sizes[k];
        if (sz == (long long)N_NODES * N_NODES)      adj = (const int*)d_in[k];
        else if (sz == (long long)N_NODES * IN_F)    x = (const float*)d_in[k];
        else if (sz == (long long)IN_F * OUT_F)      W = (const float*)d_in[k];
    }
    float* out = (float*)d_out;

    cudaFuncSetAttribute(k_aggregate, cudaFuncAttributeMaxDynamicSharedMemorySize, SMEM_AGG);

    k_gemm_h<<<N_NODES / 32, 256>>>(x, W);
    k_aggregate<<<dim3(N_NODES / BI, JSPLIT), 256, SMEM_AGG>>>(adj);
    k_finalize<<<(N_NODES * OUT_F) / 256, 256>>>(out);
}